// round 11
// baseline (speedup 1.0000x reference)
#include <cuda_runtime.h>

// ---------------------------------------------------------------------------
// Sparse 3-layer conv net (ME-style). Round 11:
//  - col-major builds + transpose bridge to row-major tables (R10, best)
//  - layer2: repacked W2 (c,c+32 adjacent) + fma.rn.f32x2, 3 issues/f
//  - tab3 chain (fill3/build3/transp3) on a forked capture stream, joined
//    before l3gs -> overlaps with layer1/layer2
//  - builds skip pad stores
// ---------------------------------------------------------------------------

#define N1S 300004        // col stride capacity, fine tables (mult of 4)
#define N2S 262148        // col stride capacity, coarse tables
#define N1_MAX 300001
#define N2_MAX 262145

// column-major staging tables (build targets)
__device__ __align__(16) int g_tc1[27 * N1S];
__device__ __align__(16) int g_tc2[8 * N2S];
__device__ __align__(16) int g_tc3[27 * N2S];
// row-major tables consumed by the layers (written by transpose)
__device__ __align__(16) int g_tab1[N1_MAX * 27];
__device__ __align__(16) int g_tab2[N2_MAX * 8];
__device__ __align__(16) int g_tab3[N2_MAX * 27];

__device__ float g_h1[(N1_MAX - 1) * 64];
__device__ float g_h2[(N2_MAX - 1) * 64];
__device__ float g_W2p[8 * 64 * 64];              // pairs (c, c+32) adjacent
__device__ float g_W3r[64 * 216];                 // W3 repacked: [f][k*8+c]
__device__ float g_S3[(N2_MAX - 1) * 216];

typedef unsigned long long ull;

__device__ __forceinline__ ull pack2(float a, float b) {
    ull r;
    asm("mov.b64 %0, {%1, %2};" : "=l"(r)
        : "r"(__float_as_uint(a)), "r"(__float_as_uint(b)));
    return r;
}
__device__ __forceinline__ ull dup2(float a) {
    ull r;
    asm("mov.b64 %0, {%1, %1};" : "=l"(r) : "r"(__float_as_uint(a)));
    return r;
}
__device__ __forceinline__ float lo2(ull v) {
    unsigned int x;
    asm("{ .reg .b32 hi; mov.b64 {%0, hi}, %1; }" : "=r"(x) : "l"(v));
    return __uint_as_float(x);
}
__device__ __forceinline__ float hi2(ull v) {
    unsigned int x;
    asm("{ .reg .b32 lo; mov.b64 {lo, %0}, %1; }" : "=r"(x) : "l"(v));
    return __uint_as_float(x);
}

// ---------------- fills (split: tabs 1&2 on main, tab3 on side stream) -------
__global__ void fill12_kernel(int n4_1, int n4_2) {
    const int4 v = make_int4(-1, -1, -1, -1);
    int t0 = blockIdx.x * blockDim.x + threadIdx.x;
    int stride = gridDim.x * blockDim.x;
    int4* p1 = (int4*)g_tc1;
    for (int i = t0; i < n4_1; i += stride) p1[i] = v;
    int4* p2 = (int4*)g_tc2;
    for (int i = t0; i < n4_2; i += stride) p2[i] = v;
}
__global__ void fill3_kernel(int n4_3) {
    const int4 v = make_int4(-1, -1, -1, -1);
    int t0 = blockIdx.x * blockDim.x + threadIdx.x;
    int stride = gridDim.x * blockDim.x;
    int4* p3 = (int4*)g_tc3;
    for (int i = t0; i < n4_3; i += stride) p3[i] = v;
}

// ---------------- merged weight repack (W2 pairs, W3r) -----------------------
__global__ void repack_all_kernel(const float* __restrict__ W2,
                                  const float* __restrict__ W3) {
    int i = blockIdx.x * blockDim.x + threadIdx.x;
    if (i < 8 * 64 * 64) {
        int kf = i >> 6, c = i & 63;
        g_W2p[(kf * 32 + (c & 31)) * 2 + (c >> 5)] = W2[i];
    }
    if (i < 27 * 512) {
        int k = i >> 9, rem = i & 511, f = rem >> 3, c = rem & 7;
        g_W3r[f * 216 + k * 8 + c] = W3[i];
    }
}

// ---------------- build: col[k*s + out] = in (coalesced; skip pads) ----------
__global__ void build_kernel(const int* __restrict__ m_in,
                             const int* __restrict__ m_out,
                             int which, int s, int L, int nout) {
    int* tab = (which == 0) ? g_tc1 : (which == 1) ? g_tc2 : g_tc3;
    int k = blockIdx.y;
    const int* mi = m_in + k * L;
    const int* mo = m_out + k * L;
    int* col = tab + k * s;
    int i = blockIdx.x * blockDim.x + threadIdx.x;
    int stride = gridDim.x * blockDim.x;
    for (; i < L; i += stride) {
        int o = mo[i];
        if (o != nout) col[o] = mi[i];
    }
}

// ---------------- transpose col-major -> row-major (tiled, coalesced) --------
template <int K>
__device__ __forceinline__ void transp_one(const int* __restrict__ cm,
                                           int* __restrict__ rm,
                                           int s, int n, int* sm) {
    int ntiles = (n + 127) >> 7;
    for (int tile = blockIdx.x; tile < ntiles; tile += gridDim.x) {
        int base = tile << 7;
        int nr = min(128, n - base);
        __syncthreads();
        for (int i = threadIdx.x; i < K * 128; i += 256) {
            int k = i >> 7, r = i & 127;
            sm[k * 129 + r] = (r < nr) ? cm[k * s + base + r] : -1;
        }
        __syncthreads();
        int total = nr * K;
        for (int i = threadIdx.x; i < total; i += 256) {
            int o = i / K, k = i - o * K;
            rm[base * K + i] = sm[k * 129 + o];
        }
    }
}

__global__ void __launch_bounds__(256) transpose12_kernel(int n1, int s1,
                                                          int n2, int s2) {
    __shared__ int sm[27 * 129];
    if (blockIdx.y == 0) transp_one<27>(g_tc1, g_tab1, s1, n1, sm);
    else                 transp_one<8>(g_tc2, g_tab2, s2, n2, sm);
}
__global__ void __launch_bounds__(256) transpose3_kernel(int n2, int s2) {
    __shared__ int sm[27 * 129];
    transp_one<27>(g_tc3, g_tab3, s2, n2, sm);
}

// ---------------- layer 1: 27 offsets, 8 -> 64, ReLU, 2 rows/warp ------------
__global__ void __launch_bounds__(256) layer1_kernel(
    const float* __restrict__ feats, const float* __restrict__ W1,
    const float* __restrict__ b1, int n1) {
    extern __shared__ float sW1[];           // 13824 floats
    for (int i = threadIdx.x; i < 27 * 512; i += 256) sW1[i] = W1[i];
    __syncthreads();

    int lane = threadIdx.x & 31;
    int gw = (blockIdx.x * 256 + threadIdx.x) >> 5;
    int nw = (gridDim.x * 256) >> 5;
    float bias0 = b1[lane], bias1 = b1[lane + 32];
    int npairs = (n1 + 1) >> 1;

    for (int p = gw; p < npairs; p += nw) {
        int o0 = 2 * p, o1 = o0 + 1;
        bool r1v = (o1 < n1);
        const int* t0 = g_tab1 + o0 * 27;
        const int* t1 = g_tab1 + o1 * 27;
        float a00 = bias0, a01 = bias1, a10 = bias0, a11 = bias1;
        for (int k = 0; k < 27; k++) {
            int i0 = t0[k];
            int i1 = r1v ? t1[k] : -1;
            if (i0 < 0 && i1 < 0) continue;
            float xf = 0.f;
            if (lane < 8) { if (i0 >= 0) xf = feats[i0 * 8 + lane]; }
            else if (lane < 16) { if (i1 >= 0) xf = feats[i1 * 8 + lane - 8]; }
            const float* w = sW1 + k * 512 + lane;
            #pragma unroll
            for (int f = 0; f < 8; f++) {
                float v0 = __shfl_sync(0xffffffffu, xf, f);
                float v1 = __shfl_sync(0xffffffffu, xf, 8 + f);
                float w0 = w[f * 64], w1 = w[f * 64 + 32];
                a00 = fmaf(v0, w0, a00);
                a01 = fmaf(v0, w1, a01);
                a10 = fmaf(v1, w0, a10);
                a11 = fmaf(v1, w1, a11);
            }
        }
        g_h1[o0 * 64 + lane]      = fmaxf(a00, 0.f);
        g_h1[o0 * 64 + lane + 32] = fmaxf(a01, 0.f);
        if (r1v) {
            g_h1[o1 * 64 + lane]      = fmaxf(a10, 0.f);
            g_h1[o1 * 64 + lane + 32] = fmaxf(a11, 0.f);
        }
    }
}

// ---------------- layer 2: 8 offsets, 64 -> 64, ReLU, f32x2 ------------------
// W2p (128 KB) in smem as (c,c+32) ull pairs; x staged pre-duplicated f32x2.
// Inner: 1 LDS.64 w + 1 LDS.64 x(bcast) + 1 FFMA2 per f; 2 accumulators.
__global__ void __launch_bounds__(512) layer2_kernel(
    const float* __restrict__ b2, int n2) {
    extern __shared__ float sm2[];
    float* sW = sm2;                          // 32768 floats (repacked)
    ull* sXd = (ull*)(sm2 + 32768);           // 16 warps * 128 ull
    {
        const float4* src = (const float4*)g_W2p;
        float4* dst = (float4*)sW;
        for (int i = threadIdx.x; i < 8192; i += 512) dst[i] = src[i];
    }
    __syncthreads();

    int lane = threadIdx.x & 31;
    int warp = threadIdx.x >> 5;
    ull* xd = sXd + warp * 128;
    int gw = (blockIdx.x * 512 + threadIdx.x) >> 5;
    int nw = (gridDim.x * 512) >> 5;
    ull bias = pack2(b2[lane], b2[lane + 32]);

    for (int o = gw; o < n2; o += nw) {
        ull a0 = bias, a1 = 0ull;
        const int* t = g_tab2 + o * 8;
        for (int k = 0; k < 8; k++) {
            int idx = t[k];                   // warp-uniform
            if (idx < 0) continue;
            float2 x0 = ((const float2*)g_h1)[idx * 32 + lane];
            xd[2 * lane]     = dup2(x0.x);
            xd[2 * lane + 1] = dup2(x0.y);
            __syncwarp();
            const ull* wp = (const ull*)sW + k * 2048 + lane;
            #pragma unroll 16
            for (int f = 0; f < 64; f += 2) {
                asm("fma.rn.f32x2 %0, %1, %2, %0;"
                    : "+l"(a0) : "l"(wp[f * 32]), "l"(xd[f]));
                asm("fma.rn.f32x2 %0, %1, %2, %0;"
                    : "+l"(a1) : "l"(wp[(f + 1) * 32]), "l"(xd[f + 1]));
            }
            __syncwarp();
        }
        ull s;
        asm("add.rn.f32x2 %0, %1, %2;" : "=l"(s) : "l"(a0), "l"(a1));
        g_h2[o * 64 + lane]      = fmaxf(lo2(s), 0.f);
        g_h2[o * 64 + lane + 32] = fmaxf(hi2(s), 0.f);
    }
}

// ---------------- layer 3 GEMM: S3[n2][216] = H2[n2][64] @ W3r[64][216] ------
__global__ void __launch_bounds__(256) l3gemm_kernel(int n2) {
    extern __shared__ float sm3[];
    float* sW = sm3;                 // 64 * 224
    float* sX = sm3 + 64 * 224;      // 64 * 64

    for (int i = threadIdx.x; i < 64 * 224; i += 256) {
        int k = i / 224, c = i - k * 224;
        sW[i] = (c < 216) ? g_W3r[k * 216 + c] : 0.f;
    }
    int base = blockIdx.x << 6;
    for (int i = threadIdx.x; i < 1024; i += 256) {
        int r = i >> 4, q = i & 15;
        int row = base + r;
        float4 v = make_float4(0.f, 0.f, 0.f, 0.f);
        if (row < n2) v = ((const float4*)g_h2)[row * 16 + q];
        ((float4*)sX)[i] = v;
    }
    __syncthreads();

    int lane = threadIdx.x & 31, warp = threadIdx.x >> 5;
    const float* xw = sX + warp * 512;

    ull acc[4][7];
    #pragma unroll
    for (int p = 0; p < 4; p++)
        #pragma unroll
        for (int j = 0; j < 7; j++) acc[p][j] = 0ull;

    #pragma unroll 4
    for (int k = 0; k < 64; k++) {
        ull xp[4];
        #pragma unroll
        for (int p = 0; p < 4; p++)
            xp[p] = pack2(xw[(2 * p) * 64 + k], xw[(2 * p + 1) * 64 + k]);
        const float* wr = sW + k * 224 + lane;
        #pragma unroll
        for (int j = 0; j < 7; j++) {
            ull ww = dup2(wr[j * 32]);
            #pragma unroll
            for (int p = 0; p < 4; p++)
                asm("fma.rn.f32x2 %0, %1, %2, %0;"
                    : "+l"(acc[p][j]) : "l"(xp[p]), "l"(ww));
        }
    }

    int rbase = base + warp * 8;
    #pragma unroll
    for (int p = 0; p < 4; p++) {
        int r0 = rbase + 2 * p;
        #pragma unroll
        for (int j = 0; j < 7; j++) {
            int col = (j << 5) + lane;
            if (col < 216) {
                if (r0 < n2)     g_S3[r0 * 216 + col]       = lo2(acc[p][j]);
                if (r0 + 1 < n2) g_S3[(r0 + 1) * 216 + col] = hi2(acc[p][j]);
            }
        }
    }
}

// ---------------- layer 3 gather-sum (row-major tab3) ------------------------
__global__ void __launch_bounds__(256) l3gs_kernel(
    const float* __restrict__ b3, float* __restrict__ out, int n2) {
    __shared__ int st[32 * 27];
    int base = blockIdx.x << 5;
    for (int i = threadIdx.x; i < 32 * 27; i += 256) {
        int o = base + i / 27;
        st[i] = (o < n2) ? g_tab3[o * 27 + i % 27] : -1;
    }
    __syncthreads();

    int lane = threadIdx.x & 31, warp = threadIdx.x >> 5;
    int sub = lane >> 3, c = lane & 7;
    int lo = (warp << 2) + sub;
    int o = base + lo;
    const int* t = st + lo * 27;
    float acc = 0.f;
    #pragma unroll
    for (int k = 0; k < 27; k++) {
        int idx = t[k];
        float v = 0.f;
        if (idx >= 0) v = g_S3[idx * 216 + (k << 3) + c];
        acc += v;
    }
    if (o < n2) out[(o << 3) + c] = acc + b3[c];
}

// ---------------------------------------------------------------------------
extern "C" void kernel_launch(void* const* d_in, const int* in_sizes, int n_in,
                              void* d_out, int out_size) {
    const float* feats = (const float*)d_in[0];
    const float* W1    = (const float*)d_in[1];
    const float* b1    = (const float*)d_in[2];
    const float* W2    = (const float*)d_in[3];
    const float* b2    = (const float*)d_in[4];
    const float* W3    = (const float*)d_in[5];
    const float* b3    = (const float*)d_in[6];
    const int* map1_in  = (const int*)d_in[7];
    const int* map1_out = (const int*)d_in[8];
    const int* map2_in  = (const int*)d_in[9];
    const int* map2_out = (const int*)d_in[10];
    const int* map3_in  = (const int*)d_in[11];
    const int* map3_out = (const int*)d_in[12];
    float* out = (float*)d_out;

    int n1 = in_sizes[0] / 8;
    int n2 = out_size / 8;
    int L1 = in_sizes[7] / 27;
    int L2 = in_sizes[9] / 8;
    int L3 = in_sizes[11] / 27;
    int s1 = (n1 + 5) & ~3;
    int s2 = (n2 + 5) & ~3;

    int smem1 = 27 * 512 * 4;
    int smem2 = 32768 * 4 + 16 * 128 * 8;
    int smem3 = (64 * 224 + 64 * 64) * 4;
    cudaFuncSetAttribute(layer1_kernel, cudaFuncAttributeMaxDynamicSharedMemorySize, smem1);
    cudaFuncSetAttribute(layer2_kernel, cudaFuncAttributeMaxDynamicSharedMemorySize, smem2);
    cudaFuncSetAttribute(l3gemm_kernel, cudaFuncAttributeMaxDynamicSharedMemorySize, smem3);

    // fork a capture side stream for the tab3 chain (independent of layers 1/2)
    cudaStream_t s3;
    cudaStreamCreateWithFlags(&s3, cudaStreamNonBlocking);
    cudaEvent_t eF, eJ;
    cudaEventCreateWithFlags(&eF, cudaEventDisableTiming);
    cudaEventCreateWithFlags(&eJ, cudaEventDisableTiming);
    cudaEventRecord(eF, 0);
    cudaStreamWaitEvent(s3, eF, 0);

    // side stream: fill3 -> build3 -> transpose3 (tab3 ready for l3gs)
    fill3_kernel<<<592, 256, 0, s3>>>((27 * s2) / 4);
    {
        dim3 g3((unsigned)min((L3 + 255) / 256, 1184), 27);
        build_kernel<<<g3, 256, 0, s3>>>(map3_in, map3_out, 2, s2, L3, n2);
    }
    transpose3_kernel<<<790, 256, 0, s3>>>(n2, s2);
    cudaEventRecord(eJ, s3);

    // main stream: tabs 1&2, repacks, layers
    fill12_kernel<<<592, 256>>>((27 * s1) / 4, (8 * s2) / 4);
    repack_all_kernel<<<128, 256>>>(W2, W3);
    {
        dim3 g1((unsigned)min((L1 + 255) / 256, 1184), 27);
        dim3 g2((unsigned)min((L2 + 255) / 256, 1184), 8);
        build_kernel<<<g1, 256>>>(map1_in, map1_out, 0, s1, L1, n1);
        build_kernel<<<g2, 256>>>(map2_in, map2_out, 1, s2, L2, n2);
    }
    transpose12_kernel<<<dim3(790, 2), 256>>>(n1, s1, n2, s2);

    layer1_kernel<<<592, 256, smem1>>>(feats, W1, b1, n1);
    layer2_kernel<<<148, 512, smem2>>>(b2, n2);
    l3gemm_kernel<<<(n2 + 63) / 64, 256, smem3>>>(n2);

    // join side stream (tab3 needed only by l3gs)
    cudaStreamWaitEvent(0, eJ, 0);
    l3gs_kernel<<<(n2 + 31) / 32, 256>>>(b3, out, n2);

    cudaEventDestroy(eF);
    cudaEventDestroy(eJ);
    cudaStreamDestroy(s3);
}

// round 13
// speedup vs baseline: 1.1005x; 1.1005x over previous
#include <cuda_runtime.h>

// ---------------------------------------------------------------------------
// Sparse 3-layer conv net (ME-style). Round 13 (= R12 with dup2 typo fixed):
//  = Round 10 (803us, best) layer/transpose/build kernels, unchanged
//  + tab3 chain (fill3/build3/transp3) forked onto a side capture stream,
//    joined just before l3gs (pure overlap with layer1/layer2/l3gemm)
//  + builds skip pad stores; wider fill grid
// ---------------------------------------------------------------------------

#define N1S 300004        // col stride capacity, fine tables (mult of 4)
#define N2S 262148        // col stride capacity, coarse tables
#define N1_MAX 300001
#define N2_MAX 262145

// column-major staging tables (build targets)
__device__ __align__(16) int g_tc1[27 * N1S];
__device__ __align__(16) int g_tc2[8 * N2S];
__device__ __align__(16) int g_tc3[27 * N2S];
// row-major tables consumed by the layers (written by transpose)
__device__ __align__(16) int g_tab1[N1_MAX * 27];
__device__ __align__(16) int g_tab2[N2_MAX * 8];
__device__ __align__(16) int g_tab3[N2_MAX * 27];

__device__ float g_h1[(N1_MAX - 1) * 64];
__device__ float g_h2[(N2_MAX - 1) * 64];
__device__ float g_W3r[64 * 216];                 // W3 repacked: [f][k*8+c]
__device__ float g_S3[(N2_MAX - 1) * 216];

typedef unsigned long long ull;

__device__ __forceinline__ ull pack2(float a, float b) {
    ull r;
    asm("mov.b64 %0, {%1, %2};" : "=l"(r)
        : "r"(__float_as_uint(a)), "r"(__float_as_uint(b)));
    return r;
}
__device__ __forceinline__ ull dup2(float a) {
    ull r;
    asm("mov.b64 %0, {%1, %1};" : "=l"(r) : "r"(__float_as_uint(a)));
    return r;
}
__device__ __forceinline__ float lo2(ull v) {
    unsigned int x;
    asm("{ .reg .b32 hi; mov.b64 {%0, hi}, %1; }" : "=r"(x) : "l"(v));
    return __uint_as_float(x);
}
__device__ __forceinline__ float hi2(ull v) {
    unsigned int x;
    asm("{ .reg .b32 lo; mov.b64 {lo, %0}, %1; }" : "=r"(x) : "l"(v));
    return __uint_as_float(x);
}

// ---------------- fills (tabs 1&2 on main, tab3 on side stream) --------------
__global__ void fill12_kernel(int n4_1, int n4_2) {
    const int4 v = make_int4(-1, -1, -1, -1);
    int t0 = blockIdx.x * blockDim.x + threadIdx.x;
    int stride = gridDim.x * blockDim.x;
    int4* p1 = (int4*)g_tc1;
    for (int i = t0; i < n4_1; i += stride) p1[i] = v;
    int4* p2 = (int4*)g_tc2;
    for (int i = t0; i < n4_2; i += stride) p2[i] = v;
}
__global__ void fill3_kernel(int n4_3) {
    const int4 v = make_int4(-1, -1, -1, -1);
    int t0 = blockIdx.x * blockDim.x + threadIdx.x;
    int stride = gridDim.x * blockDim.x;
    int4* p3 = (int4*)g_tc3;
    for (int i = t0; i < n4_3; i += stride) p3[i] = v;
}

// ---------------- W3 repack: W3r[f*216 + k*8 + c] = W3[k][f][c] --------------
__global__ void repack_w3_kernel(const float* __restrict__ W3) {
    int i = blockIdx.x * blockDim.x + threadIdx.x;
    if (i < 27 * 512) {
        int k = i >> 9, rem = i & 511, f = rem >> 3, c = rem & 7;
        g_W3r[f * 216 + k * 8 + c] = W3[i];
    }
}

// ---------------- build: col[k*s + out] = in (coalesced; skip pads) ----------
__global__ void build_kernel(const int* __restrict__ m_in,
                             const int* __restrict__ m_out,
                             int which, int s, int L, int nout) {
    int* tab = (which == 0) ? g_tc1 : (which == 1) ? g_tc2 : g_tc3;
    int k = blockIdx.y;
    const int* mi = m_in + k * L;
    const int* mo = m_out + k * L;
    int* col = tab + k * s;
    int i = blockIdx.x * blockDim.x + threadIdx.x;
    int stride = gridDim.x * blockDim.x;
    for (; i < L; i += stride) {
        int o = mo[i];
        if (o != nout) col[o] = mi[i];
    }
}

// ---------------- transpose col-major -> row-major (tiled, coalesced) --------
template <int K>
__device__ __forceinline__ void transp_one(const int* __restrict__ cm,
                                           int* __restrict__ rm,
                                           int s, int n, int* sm) {
    int ntiles = (n + 127) >> 7;
    for (int tile = blockIdx.x; tile < ntiles; tile += gridDim.x) {
        int base = tile << 7;
        int nr = min(128, n - base);
        __syncthreads();
        for (int i = threadIdx.x; i < K * 128; i += 256) {
            int k = i >> 7, r = i & 127;
            sm[k * 129 + r] = (r < nr) ? cm[k * s + base + r] : -1;
        }
        __syncthreads();
        int total = nr * K;
        for (int i = threadIdx.x; i < total; i += 256) {
            int o = i / K, k = i - o * K;
            rm[base * K + i] = sm[k * 129 + o];
        }
    }
}

__global__ void __launch_bounds__(256) transpose12_kernel(int n1, int s1,
                                                          int n2, int s2) {
    __shared__ int sm[27 * 129];
    if (blockIdx.y == 0) transp_one<27>(g_tc1, g_tab1, s1, n1, sm);
    else                 transp_one<8>(g_tc2, g_tab2, s2, n2, sm);
}
__global__ void __launch_bounds__(256) transpose3_kernel(int n2, int s2) {
    __shared__ int sm[27 * 129];
    transp_one<27>(g_tc3, g_tab3, s2, n2, sm);
}

// ---------------- layer 1: 27 offsets, 8 -> 64, ReLU, 2 rows/warp ------------
__global__ void __launch_bounds__(256) layer1_kernel(
    const float* __restrict__ feats, const float* __restrict__ W1,
    const float* __restrict__ b1, int n1) {
    extern __shared__ float sW1[];           // 13824 floats
    for (int i = threadIdx.x; i < 27 * 512; i += 256) sW1[i] = W1[i];
    __syncthreads();

    int lane = threadIdx.x & 31;
    int gw = (blockIdx.x * 256 + threadIdx.x) >> 5;
    int nw = (gridDim.x * 256) >> 5;
    float bias0 = b1[lane], bias1 = b1[lane + 32];
    int npairs = (n1 + 1) >> 1;

    for (int p = gw; p < npairs; p += nw) {
        int o0 = 2 * p, o1 = o0 + 1;
        bool r1v = (o1 < n1);
        const int* t0 = g_tab1 + o0 * 27;
        const int* t1 = g_tab1 + o1 * 27;
        float a00 = bias0, a01 = bias1, a10 = bias0, a11 = bias1;
        for (int k = 0; k < 27; k++) {
            int i0 = t0[k];
            int i1 = r1v ? t1[k] : -1;
            if (i0 < 0 && i1 < 0) continue;
            float xf = 0.f;
            if (lane < 8) { if (i0 >= 0) xf = feats[i0 * 8 + lane]; }
            else if (lane < 16) { if (i1 >= 0) xf = feats[i1 * 8 + lane - 8]; }
            const float* w = sW1 + k * 512 + lane;
            #pragma unroll
            for (int f = 0; f < 8; f++) {
                float v0 = __shfl_sync(0xffffffffu, xf, f);
                float v1 = __shfl_sync(0xffffffffu, xf, 8 + f);
                float w0 = w[f * 64], w1 = w[f * 64 + 32];
                a00 = fmaf(v0, w0, a00);
                a01 = fmaf(v0, w1, a01);
                a10 = fmaf(v1, w0, a10);
                a11 = fmaf(v1, w1, a11);
            }
        }
        g_h1[o0 * 64 + lane]      = fmaxf(a00, 0.f);
        g_h1[o0 * 64 + lane + 32] = fmaxf(a01, 0.f);
        if (r1v) {
            g_h1[o1 * 64 + lane]      = fmaxf(a10, 0.f);
            g_h1[o1 * 64 + lane + 32] = fmaxf(a11, 0.f);
        }
    }
}

// ---------------- layer 2: 8 offsets, 64 -> 64, ReLU (R10/R6 version) --------
__global__ void __launch_bounds__(512) layer2_kernel(
    const float* __restrict__ W2, const float* __restrict__ b2, int n2) {
    extern __shared__ float sm2[];
    float* sW = sm2;                          // 32768 floats
    float* sX = sm2 + 32768;                  // 16 warps * 64 floats
    for (int i = threadIdx.x; i < 32768; i += 512) sW[i] = W2[i];
    __syncthreads();

    int lane = threadIdx.x & 31;
    int warp = threadIdx.x >> 5;
    float* xw = sX + warp * 64;
    int gw = (blockIdx.x * 512 + threadIdx.x) >> 5;
    int nw = (gridDim.x * 512) >> 5;
    float bias0 = b2[lane], bias1 = b2[lane + 32];

    for (int o = gw; o < n2; o += nw) {
        float a0 = bias0, a1 = bias1;
        const int* t = g_tab2 + o * 8;
        for (int k = 0; k < 8; k++) {
            int idx = t[k];                   // warp-uniform
            if (idx < 0) continue;
            xw[lane]      = g_h1[idx * 64 + lane];
            xw[lane + 32] = g_h1[idx * 64 + lane + 32];
            __syncwarp();
            const float* w = sW + k * 4096 + lane;
            #pragma unroll
            for (int f = 0; f < 64; f++) {
                float v = xw[f];
                a0 = fmaf(v, w[f * 64], a0);
                a1 = fmaf(v, w[f * 64 + 32], a1);
            }
            __syncwarp();
        }
        g_h2[o * 64 + lane]      = fmaxf(a0, 0.f);
        g_h2[o * 64 + lane + 32] = fmaxf(a1, 0.f);
    }
}

// ---------------- layer 3 GEMM: S3[n2][216] = H2[n2][64] @ W3r[64][216] ------
__global__ void __launch_bounds__(256) l3gemm_kernel(int n2) {
    extern __shared__ float sm3[];
    float* sW = sm3;                 // 64 * 224
    float* sX = sm3 + 64 * 224;      // 64 * 64

    for (int i = threadIdx.x; i < 64 * 224; i += 256) {
        int k = i / 224, c = i - k * 224;
        sW[i] = (c < 216) ? g_W3r[k * 216 + c] : 0.f;
    }
    int base = blockIdx.x << 6;
    for (int i = threadIdx.x; i < 1024; i += 256) {
        int r = i >> 4, q = i & 15;
        int row = base + r;
        float4 v = make_float4(0.f, 0.f, 0.f, 0.f);
        if (row < n2) v = ((const float4*)g_h2)[row * 16 + q];
        ((float4*)sX)[i] = v;
    }
    __syncthreads();

    int lane = threadIdx.x & 31, warp = threadIdx.x >> 5;
    const float* xw = sX + warp * 512;

    ull acc[4][7];
    #pragma unroll
    for (int p = 0; p < 4; p++)
        #pragma unroll
        for (int j = 0; j < 7; j++) acc[p][j] = 0ull;

    #pragma unroll 4
    for (int k = 0; k < 64; k++) {
        ull xp[4];
        #pragma unroll
        for (int p = 0; p < 4; p++)
            xp[p] = pack2(xw[(2 * p) * 64 + k], xw[(2 * p + 1) * 64 + k]);
        const float* wr = sW + k * 224 + lane;
        #pragma unroll
        for (int j = 0; j < 7; j++) {
            ull ww = dup2(wr[j * 32]);
            #pragma unroll
            for (int p = 0; p < 4; p++)
                asm("fma.rn.f32x2 %0, %1, %2, %0;"
                    : "+l"(acc[p][j]) : "l"(xp[p]), "l"(ww));
        }
    }

    int rbase = base + warp * 8;
    #pragma unroll
    for (int p = 0; p < 4; p++) {
        int r0 = rbase + 2 * p;
        #pragma unroll
        for (int j = 0; j < 7; j++) {
            int col = (j << 5) + lane;
            if (col < 216) {
                if (r0 < n2)     g_S3[r0 * 216 + col]       = lo2(acc[p][j]);
                if (r0 + 1 < n2) g_S3[(r0 + 1) * 216 + col] = hi2(acc[p][j]);
            }
        }
    }
}

// ---------------- layer 3 gather-sum (row-major tab3) ------------------------
__global__ void __launch_bounds__(256) l3gs_kernel(
    const float* __restrict__ b3, float* __restrict__ out, int n2) {
    __shared__ int st[32 * 27];
    int base = blockIdx.x << 5;
    for (int i = threadIdx.x; i < 32 * 27; i += 256) {
        int o = base + i / 27;
        st[i] = (o < n2) ? g_tab3[o * 27 + i % 27] : -1;
    }
    __syncthreads();

    int lane = threadIdx.x & 31, warp = threadIdx.x >> 5;
    int sub = lane >> 3, c = lane & 7;
    int lo = (warp << 2) + sub;
    int o = base + lo;
    const int* t = st + lo * 27;
    float acc = 0.f;
    #pragma unroll
    for (int k = 0; k < 27; k++) {
        int idx = t[k];
        float v = 0.f;
        if (idx >= 0) v = g_S3[idx * 216 + (k << 3) + c];
        acc += v;
    }
    if (o < n2) out[(o << 3) + c] = acc + b3[c];
}

// ---------------------------------------------------------------------------
extern "C" void kernel_launch(void* const* d_in, const int* in_sizes, int n_in,
                              void* d_out, int out_size) {
    const float* feats = (const float*)d_in[0];
    const float* W1    = (const float*)d_in[1];
    const float* b1    = (const float*)d_in[2];
    const float* W2    = (const float*)d_in[3];
    const float* b2    = (const float*)d_in[4];
    const float* W3    = (const float*)d_in[5];
    const float* b3    = (const float*)d_in[6];
    const int* map1_in  = (const int*)d_in[7];
    const int* map1_out = (const int*)d_in[8];
    const int* map2_in  = (const int*)d_in[9];
    const int* map2_out = (const int*)d_in[10];
    const int* map3_in  = (const int*)d_in[11];
    const int* map3_out = (const int*)d_in[12];
    float* out = (float*)d_out;

    int n1 = in_sizes[0] / 8;
    int n2 = out_size / 8;
    int L1 = in_sizes[7] / 27;
    int L2 = in_sizes[9] / 8;
    int L3 = in_sizes[11] / 27;
    int s1 = (n1 + 5) & ~3;
    int s2 = (n2 + 5) & ~3;

    int smem1 = 27 * 512 * 4;
    int smem2 = (32768 + 16 * 64) * 4;
    int smem3 = (64 * 224 + 64 * 64) * 4;
    cudaFuncSetAttribute(layer1_kernel, cudaFuncAttributeMaxDynamicSharedMemorySize, smem1);
    cudaFuncSetAttribute(layer2_kernel, cudaFuncAttributeMaxDynamicSharedMemorySize, smem2);
    cudaFuncSetAttribute(l3gemm_kernel, cudaFuncAttributeMaxDynamicSharedMemorySize, smem3);

    // fork a capture side stream for the tab3 chain (independent of layers 1/2)
    cudaStream_t s3;
    cudaStreamCreateWithFlags(&s3, cudaStreamNonBlocking);
    cudaEvent_t eF, eJ;
    cudaEventCreateWithFlags(&eF, cudaEventDisableTiming);
    cudaEventCreateWithFlags(&eJ, cudaEventDisableTiming);
    cudaEventRecord(eF, 0);
    cudaStreamWaitEvent(s3, eF, 0);

    // side stream: fill3 -> build3 -> transpose3 (tab3 ready for l3gs)
    fill3_kernel<<<592, 256, 0, s3>>>((27 * s2) / 4);
    {
        dim3 g3((unsigned)min((L3 + 255) / 256, 1184), 27);
        build_kernel<<<g3, 256, 0, s3>>>(map3_in, map3_out, 2, s2, L3, n2);
    }
    transpose3_kernel<<<790, 256, 0, s3>>>(n2, s2);
    cudaEventRecord(eJ, s3);

    // main stream: tabs 1&2, repack, layers (R10 kernels)
    fill12_kernel<<<1184, 256>>>((27 * s1) / 4, (8 * s2) / 4);
    repack_w3_kernel<<<54, 256>>>(W3);
    {
        dim3 g1((unsigned)min((L1 + 255) / 256, 1184), 27);
        dim3 g2((unsigned)min((L2 + 255) / 256, 1184), 8);
        build_kernel<<<g1, 256>>>(map1_in, map1_out, 0, s1, L1, n1);
        build_kernel<<<g2, 256>>>(map2_in, map2_out, 1, s2, L2, n2);
    }
    transpose12_kernel<<<dim3(790, 2), 256>>>(n1, s1, n2, s2);

    layer1_kernel<<<592, 256, smem1>>>(feats, W1, b1, n1);
    layer2_kernel<<<148, 512, smem2>>>(W2, b2, n2);
    l3gemm_kernel<<<(n2 + 63) / 64, 256, smem3>>>(n2);

    // join side stream (tab3 needed only by l3gs)
    cudaStreamWaitEvent(0, eJ, 0);
    l3gs_kernel<<<(n2 + 31) / 32, 256>>>(b3, out, n2);

    cudaEventDestroy(eF);
    cudaEventDestroy(eJ);
    cudaStreamDestroy(s3);
}

// round 15
// speedup vs baseline: 1.1263x; 1.0234x over previous
#include <cuda_runtime.h>

// ---------------------------------------------------------------------------
// Sparse 3-layer conv net (ME-style). Round 14:
//  = Round 13 kernels (788us best), with:
//  + full 3-stream fork/join: main = tab1 chain -> layers; sideA = tab2 chain
//    (joined before layer2); sideB = tab3 chain + W3 repack (joined before
//    l3gemm). Independent table prep fully overlapped with layers.
//  + layer2 at 1024 threads/block (32 warps/SM, same inner loop)
// ---------------------------------------------------------------------------

#define N1S 300004        // col stride capacity, fine tables (mult of 4)
#define N2S 262148        // col stride capacity, coarse tables
#define N1_MAX 300001
#define N2_MAX 262145

// column-major staging tables (build targets)
__device__ __align__(16) int g_tc1[27 * N1S];
__device__ __align__(16) int g_tc2[8 * N2S];
__device__ __align__(16) int g_tc3[27 * N2S];
// row-major tables consumed by the layers (written by transpose)
__device__ __align__(16) int g_tab1[N1_MAX * 27];
__device__ __align__(16) int g_tab2[N2_MAX * 8];
__device__ __align__(16) int g_tab3[N2_MAX * 27];

__device__ float g_h1[(N1_MAX - 1) * 64];
__device__ float g_h2[(N2_MAX - 1) * 64];
__device__ float g_W3r[64 * 216];                 // W3 repacked: [f][k*8+c]
__device__ float g_S3[(N2_MAX - 1) * 216];

typedef unsigned long long ull;

__device__ __forceinline__ ull pack2(float a, float b) {
    ull r;
    asm("mov.b64 %0, {%1, %2};" : "=l"(r)
        : "r"(__float_as_uint(a)), "r"(__float_as_uint(b)));
    return r;
}
__device__ __forceinline__ ull dup2(float a) {
    ull r;
    asm("mov.b64 %0, {%1, %1};" : "=l"(r) : "r"(__float_as_uint(a)));
    return r;
}
__device__ __forceinline__ float lo2(ull v) {
    unsigned int x;
    asm("{ .reg .b32 hi; mov.b64 {%0, hi}, %1; }" : "=r"(x) : "l"(v));
    return __uint_as_float(x);
}
__device__ __forceinline__ float hi2(ull v) {
    unsigned int x;
    asm("{ .reg .b32 lo; mov.b64 {lo, %0}, %1; }" : "=r"(x) : "l"(v));
    return __uint_as_float(x);
}

// ---------------- per-table fills ----------------
__global__ void fill1_kernel(int n4) {
    const int4 v = make_int4(-1, -1, -1, -1);
    int i = blockIdx.x * blockDim.x + threadIdx.x;
    int stride = gridDim.x * blockDim.x;
    int4* p = (int4*)g_tc1;
    for (; i < n4; i += stride) p[i] = v;
}
__global__ void fill2_kernel(int n4) {
    const int4 v = make_int4(-1, -1, -1, -1);
    int i = blockIdx.x * blockDim.x + threadIdx.x;
    int stride = gridDim.x * blockDim.x;
    int4* p = (int4*)g_tc2;
    for (; i < n4; i += stride) p[i] = v;
}
__global__ void fill3_kernel(int n4) {
    const int4 v = make_int4(-1, -1, -1, -1);
    int i = blockIdx.x * blockDim.x + threadIdx.x;
    int stride = gridDim.x * blockDim.x;
    int4* p = (int4*)g_tc3;
    for (; i < n4; i += stride) p[i] = v;
}

// ---------------- W3 repack: W3r[f*216 + k*8 + c] = W3[k][f][c] --------------
__global__ void repack_w3_kernel(const float* __restrict__ W3) {
    int i = blockIdx.x * blockDim.x + threadIdx.x;
    if (i < 27 * 512) {
        int k = i >> 9, rem = i & 511, f = rem >> 3, c = rem & 7;
        g_W3r[f * 216 + k * 8 + c] = W3[i];
    }
}

// ---------------- build: col[k*s + out] = in (coalesced; skip pads) ----------
__global__ void build_kernel(const int* __restrict__ m_in,
                             const int* __restrict__ m_out,
                             int which, int s, int L, int nout) {
    int* tab = (which == 0) ? g_tc1 : (which == 1) ? g_tc2 : g_tc3;
    int k = blockIdx.y;
    const int* mi = m_in + k * L;
    const int* mo = m_out + k * L;
    int* col = tab + k * s;
    int i = blockIdx.x * blockDim.x + threadIdx.x;
    int stride = gridDim.x * blockDim.x;
    for (; i < L; i += stride) {
        int o = mo[i];
        if (o != nout) col[o] = mi[i];
    }
}

// ---------------- transpose col-major -> row-major (tiled, coalesced) --------
template <int K>
__device__ __forceinline__ void transp_one(const int* __restrict__ cm,
                                           int* __restrict__ rm,
                                           int s, int n, int* sm) {
    int ntiles = (n + 127) >> 7;
    for (int tile = blockIdx.x; tile < ntiles; tile += gridDim.x) {
        int base = tile << 7;
        int nr = min(128, n - base);
        __syncthreads();
        for (int i = threadIdx.x; i < K * 128; i += 256) {
            int k = i >> 7, r = i & 127;
            sm[k * 129 + r] = (r < nr) ? cm[k * s + base + r] : -1;
        }
        __syncthreads();
        int total = nr * K;
        for (int i = threadIdx.x; i < total; i += 256) {
            int o = i / K, k = i - o * K;
            rm[base * K + i] = sm[k * 129 + o];
        }
    }
}

__global__ void __launch_bounds__(256) transpose1_kernel(int n1, int s1) {
    __shared__ int sm[27 * 129];
    transp_one<27>(g_tc1, g_tab1, s1, n1, sm);
}
__global__ void __launch_bounds__(256) transpose2_kernel(int n2, int s2) {
    __shared__ int sm[8 * 129];
    transp_one<8>(g_tc2, g_tab2, s2, n2, sm);
}
__global__ void __launch_bounds__(256) transpose3_kernel(int n2, int s2) {
    __shared__ int sm[27 * 129];
    transp_one<27>(g_tc3, g_tab3, s2, n2, sm);
}

// ---------------- layer 1: 27 offsets, 8 -> 64, ReLU, 2 rows/warp ------------
__global__ void __launch_bounds__(256) layer1_kernel(
    const float* __restrict__ feats, const float* __restrict__ W1,
    const float* __restrict__ b1, int n1) {
    extern __shared__ float sW1[];           // 13824 floats
    for (int i = threadIdx.x; i < 27 * 512; i += 256) sW1[i] = W1[i];
    __syncthreads();

    int lane = threadIdx.x & 31;
    int gw = (blockIdx.x * 256 + threadIdx.x) >> 5;
    int nw = (gridDim.x * 256) >> 5;
    float bias0 = b1[lane], bias1 = b1[lane + 32];
    int npairs = (n1 + 1) >> 1;

    for (int p = gw; p < npairs; p += nw) {
        int o0 = 2 * p, o1 = o0 + 1;
        bool r1v = (o1 < n1);
        const int* t0 = g_tab1 + o0 * 27;
        const int* t1 = g_tab1 + o1 * 27;
        float a00 = bias0, a01 = bias1, a10 = bias0, a11 = bias1;
        for (int k = 0; k < 27; k++) {
            int i0 = t0[k];
            int i1 = r1v ? t1[k] : -1;
            if (i0 < 0 && i1 < 0) continue;
            float xf = 0.f;
            if (lane < 8) { if (i0 >= 0) xf = feats[i0 * 8 + lane]; }
            else if (lane < 16) { if (i1 >= 0) xf = feats[i1 * 8 + lane - 8]; }
            const float* w = sW1 + k * 512 + lane;
            #pragma unroll
            for (int f = 0; f < 8; f++) {
                float v0 = __shfl_sync(0xffffffffu, xf, f);
                float v1 = __shfl_sync(0xffffffffu, xf, 8 + f);
                float w0 = w[f * 64], w1 = w[f * 64 + 32];
                a00 = fmaf(v0, w0, a00);
                a01 = fmaf(v0, w1, a01);
                a10 = fmaf(v1, w0, a10);
                a11 = fmaf(v1, w1, a11);
            }
        }
        g_h1[o0 * 64 + lane]      = fmaxf(a00, 0.f);
        g_h1[o0 * 64 + lane + 32] = fmaxf(a01, 0.f);
        if (r1v) {
            g_h1[o1 * 64 + lane]      = fmaxf(a10, 0.f);
            g_h1[o1 * 64 + lane + 32] = fmaxf(a11, 0.f);
        }
    }
}

// ---------------- layer 2: 8 offsets, 64 -> 64, ReLU (1024 threads) ----------
__global__ void __launch_bounds__(1024) layer2_kernel(
    const float* __restrict__ W2, const float* __restrict__ b2, int n2) {
    extern __shared__ float sm2[];
    float* sW = sm2;                          // 32768 floats
    float* sX = sm2 + 32768;                  // 32 warps * 64 floats
    for (int i = threadIdx.x; i < 32768; i += 1024) sW[i] = W2[i];
    __syncthreads();

    int lane = threadIdx.x & 31;
    int warp = threadIdx.x >> 5;
    float* xw = sX + warp * 64;
    int gw = (blockIdx.x * 1024 + threadIdx.x) >> 5;
    int nw = (gridDim.x * 1024) >> 5;
    float bias0 = b2[lane], bias1 = b2[lane + 32];

    for (int o = gw; o < n2; o += nw) {
        float a0 = bias0, a1 = bias1;
        const int* t = g_tab2 + o * 8;
        for (int k = 0; k < 8; k++) {
            int idx = t[k];                   // warp-uniform
            if (idx < 0) continue;
            xw[lane]      = g_h1[idx * 64 + lane];
            xw[lane + 32] = g_h1[idx * 64 + lane + 32];
            __syncwarp();
            const float* w = sW + k * 4096 + lane;
            #pragma unroll
            for (int f = 0; f < 64; f++) {
                float v = xw[f];
                a0 = fmaf(v, w[f * 64], a0);
                a1 = fmaf(v, w[f * 64 + 32], a1);
            }
            __syncwarp();
        }
        g_h2[o * 64 + lane]      = fmaxf(a0, 0.f);
        g_h2[o * 64 + lane + 32] = fmaxf(a1, 0.f);
    }
}

// ---------------- layer 3 GEMM: S3[n2][216] = H2[n2][64] @ W3r[64][216] ------
__global__ void __launch_bounds__(256) l3gemm_kernel(int n2) {
    extern __shared__ float sm3[];
    float* sW = sm3;                 // 64 * 224
    float* sX = sm3 + 64 * 224;      // 64 * 64

    for (int i = threadIdx.x; i < 64 * 224; i += 256) {
        int k = i / 224, c = i - k * 224;
        sW[i] = (c < 216) ? g_W3r[k * 216 + c] : 0.f;
    }
    int base = blockIdx.x << 6;
    for (int i = threadIdx.x; i < 1024; i += 256) {
        int r = i >> 4, q = i & 15;
        int row = base + r;
        float4 v = make_float4(0.f, 0.f, 0.f, 0.f);
        if (row < n2) v = ((const float4*)g_h2)[row * 16 + q];
        ((float4*)sX)[i] = v;
    }
    __syncthreads();

    int lane = threadIdx.x & 31, warp = threadIdx.x >> 5;
    const float* xw = sX + warp * 512;

    ull acc[4][7];
    #pragma unroll
    for (int p = 0; p < 4; p++)
        #pragma unroll
        for (int j = 0; j < 7; j++) acc[p][j] = 0ull;

    #pragma unroll 4
    for (int k = 0; k < 64; k++) {
        ull xp[4];
        #pragma unroll
        for (int p = 0; p < 4; p++)
            xp[p] = pack2(xw[(2 * p) * 64 + k], xw[(2 * p + 1) * 64 + k]);
        const float* wr = sW + k * 224 + lane;
        #pragma unroll
        for (int j = 0; j < 7; j++) {
            ull ww = dup2(wr[j * 32]);
            #pragma unroll
            for (int p = 0; p < 4; p++)
                asm("fma.rn.f32x2 %0, %1, %2, %0;"
                    : "+l"(acc[p][j]) : "l"(xp[p]), "l"(ww));
        }
    }

    int rbase = base + warp * 8;
    #pragma unroll
    for (int p = 0; p < 4; p++) {
        int r0 = rbase + 2 * p;
        #pragma unroll
        for (int j = 0; j < 7; j++) {
            int col = (j << 5) + lane;
            if (col < 216) {
                if (r0 < n2)     g_S3[r0 * 216 + col]       = lo2(acc[p][j]);
                if (r0 + 1 < n2) g_S3[(r0 + 1) * 216 + col] = hi2(acc[p][j]);
            }
        }
    }
}

// ---------------- layer 3 gather-sum (row-major tab3) ------------------------
__global__ void __launch_bounds__(256) l3gs_kernel(
    const float* __restrict__ b3, float* __restrict__ out, int n2) {
    __shared__ int st[32 * 27];
    int base = blockIdx.x << 5;
    for (int i = threadIdx.x; i < 32 * 27; i += 256) {
        int o = base + i / 27;
        st[i] = (o < n2) ? g_tab3[o * 27 + i % 27] : -1;
    }
    __syncthreads();

    int lane = threadIdx.x & 31, warp = threadIdx.x >> 5;
    int sub = lane >> 3, c = lane & 7;
    int lo = (warp << 2) + sub;
    int o = base + lo;
    const int* t = st + lo * 27;
    float acc = 0.f;
    #pragma unroll
    for (int k = 0; k < 27; k++) {
        int idx = t[k];
        float v = 0.f;
        if (idx >= 0) v = g_S3[idx * 216 + (k << 3) + c];
        acc += v;
    }
    if (o < n2) out[(o << 3) + c] = acc + b3[c];
}

// ---------------------------------------------------------------------------
extern "C" void kernel_launch(void* const* d_in, const int* in_sizes, int n_in,
                              void* d_out, int out_size) {
    const float* feats = (const float*)d_in[0];
    const float* W1    = (const float*)d_in[1];
    const float* b1    = (const float*)d_in[2];
    const float* W2    = (const float*)d_in[3];
    const float* b2    = (const float*)d_in[4];
    const float* W3    = (const float*)d_in[5];
    const float* b3    = (const float*)d_in[6];
    const int* map1_in  = (const int*)d_in[7];
    const int* map1_out = (const int*)d_in[8];
    const int* map2_in  = (const int*)d_in[9];
    const int* map2_out = (const int*)d_in[10];
    const int* map3_in  = (const int*)d_in[11];
    const int* map3_out = (const int*)d_in[12];
    float* out = (float*)d_out;

    int n1 = in_sizes[0] / 8;
    int n2 = out_size / 8;
    int L1 = in_sizes[7] / 27;
    int L2 = in_sizes[9] / 8;
    int L3 = in_sizes[11] / 27;
    int s1 = (n1 + 5) & ~3;
    int s2 = (n2 + 5) & ~3;

    int smem1 = 27 * 512 * 4;
    int smem2 = (32768 + 32 * 64) * 4;
    int smem3 = (64 * 224 + 64 * 64) * 4;
    cudaFuncSetAttribute(layer1_kernel, cudaFuncAttributeMaxDynamicSharedMemorySize, smem1);
    cudaFuncSetAttribute(layer2_kernel, cudaFuncAttributeMaxDynamicSharedMemorySize, smem2);
    cudaFuncSetAttribute(l3gemm_kernel, cudaFuncAttributeMaxDynamicSharedMemorySize, smem3);

    // fork two side capture streams
    cudaStream_t sA, sB;
    cudaStreamCreateWithFlags(&sA, cudaStreamNonBlocking);
    cudaStreamCreateWithFlags(&sB, cudaStreamNonBlocking);
    cudaEvent_t eF, eA, eB;
    cudaEventCreateWithFlags(&eF, cudaEventDisableTiming);
    cudaEventCreateWithFlags(&eA, cudaEventDisableTiming);
    cudaEventCreateWithFlags(&eB, cudaEventDisableTiming);
    cudaEventRecord(eF, 0);
    cudaStreamWaitEvent(sA, eF, 0);
    cudaStreamWaitEvent(sB, eF, 0);

    // sideA: tab2 chain (needed by layer2)
    fill2_kernel<<<296, 256, 0, sA>>>((8 * s2) / 4);
    {
        dim3 g2((unsigned)min((L2 + 255) / 256, 1184), 8);
        build_kernel<<<g2, 256, 0, sA>>>(map2_in, map2_out, 1, s2, L2, n2);
    }
    transpose2_kernel<<<790, 256, 0, sA>>>(n2, s2);
    cudaEventRecord(eA, sA);

    // sideB: tab3 chain + W3 repack (needed by l3gemm/l3gs)
    fill3_kernel<<<592, 256, 0, sB>>>((27 * s2) / 4);
    {
        dim3 g3((unsigned)min((L3 + 255) / 256, 1184), 27);
        build_kernel<<<g3, 256, 0, sB>>>(map3_in, map3_out, 2, s2, L3, n2);
    }
    transpose3_kernel<<<790, 256, 0, sB>>>(n2, s2);
    repack_w3_kernel<<<54, 256, 0, sB>>>(W3);
    cudaEventRecord(eB, sB);

    // main: tab1 chain -> layer1
    fill1_kernel<<<592, 256>>>((27 * s1) / 4);
    {
        dim3 g1((unsigned)min((L1 + 255) / 256, 1184), 27);
        build_kernel<<<g1, 256>>>(map1_in, map1_out, 0, s1, L1, n1);
    }
    transpose1_kernel<<<790, 256>>>(n1, s1);
    layer1_kernel<<<592, 256, smem1>>>(feats, W1, b1, n1);

    // join A, then layer2
    cudaStreamWaitEvent(0, eA, 0);
    layer2_kernel<<<148, 1024, smem2>>>(W2, b2, n2);

    // join B, then l3gemm + l3gs
    cudaStreamWaitEvent(0, eB, 0);
    l3gemm_kernel<<<(n2 + 63) / 64, 256, smem3>>>(n2);
    l3gs_kernel<<<(n2 + 31) / 32, 256>>>(b3, out, n2);

    cudaEventDestroy(eF);
    cudaEventDestroy(eA);
    cudaEventDestroy(eB);
    cudaStreamDestroy(sA);
    cudaStreamDestroy(sB);
}